// round 15
// baseline (speedup 1.0000x reference)
#include <cuda_runtime.h>
#include <cuda_fp16.h>
#include <cstdint>

#define NROWS   1152
#define OUT_CH  32
#define THREADS 768                // 24 warps; 2 CTAs/SM -> 48 warps
#define NWARP   24
#define HRPT    3                  // half-rows per thread (2304/768)
#define ROWU32  16                 // 64B/row, chunk-XOR swizzled
#define F4PT    12                 // float4 gmem loads per thread
#define LOG2E   1.4426950408889634f
#define STAGGER_CYC 6000ull        // ~3.3us @1.8GHz: half a CTA's DRAM share

__device__ __forceinline__ float rcpa(float x) {
    float y; asm("rcp.approx.f32 %0, %1;" : "=f"(y) : "f"(x)); return y;
}
__device__ __forceinline__ unsigned ex2_h2(unsigned a) {
    unsigned y; asm("ex2.approx.f16x2 %0, %1;" : "=r"(y) : "r"(a)); return y;
}
__device__ __forceinline__ float warp_sum(float v) {
    v += __shfl_xor_sync(0xffffffffu, v, 16);
    v += __shfl_xor_sync(0xffffffffu, v, 8);
    v += __shfl_xor_sync(0xffffffffu, v, 4);
    v += __shfl_xor_sync(0xffffffffu, v, 2);
    v += __shfl_xor_sync(0xffffffffu, v, 1);
    return v;
}
__device__ __forceinline__ unsigned h2u(__half2 h)  { return *(unsigned*)&h; }
__device__ __forceinline__ __half2  u2h(unsigned u) { return *(__half2*)&u; }

// One CTA per sample, 2 CTAs/SM (48 warps), half-row-per-thread sweeps (R12).
// New: the two co-resident CTA slots are DESYNCED by ~half a load phase
// (clock64 spin on the second wave-1 slot). One CTA streams from DRAM while
// its partner sweeps; the offset self-perpetuates through work-stealing, so
// DRAM stays busy across the whole wave instead of bursting.
__global__ __launch_bounds__(THREADS, 2)
void caps_kernel(const float* __restrict__ u_hat,
                 const float* __restrict__ cprior,
                 float* __restrict__ out,
                 int nSM)
{
    extern __shared__ unsigned smu[];
    unsigned* U   = smu;                            // [1152][16] u32 (half2)
    float*    RED = (float*)(smu + NROWS * ROWU32); // [24][32] (pass-0 & sweeps)
    unsigned* V2  = (unsigned*)(RED + NWARP * OUT_CH); // [16] packed v*log2e

    const int tid  = threadIdx.x;
    const int lane = tid & 31;
    const int warp = tid >> 5;
    const int par  = tid & 1;                       // half parity
    const size_t base = (size_t)blockIdx.x * (NROWS * OUT_CH);

    // ---- stagger: second wave-1 SM slot starts ~3.3us late; the offset
    // persists via slot-freeing times. Only wave 1 pays the delay.
    if ((blockIdx.x / nSM) & 1) {
        unsigned long long t0 = clock64();
        while (clock64() - t0 < STAGGER_CYC) { }
    }

    // ---- coalesced fp32 load, fused exact pass-0 dot, swizzled fp16 store ----
    const int cg = (4 * tid) & 31;
    const float4 cj = __ldg((const float4*)(cprior + cg));  // row-uniform prior
    float4 s0 = make_float4(0.f, 0.f, 0.f, 0.f);
#pragma unroll
    for (int k = 0; k < F4PT; k++) {
        const int e   = (tid + THREADS * k) << 2;
        const int row = e >> 5;
        const float4 u = __ldg((const float4*)(u_hat + base + e));
        s0.x = fmaf(u.x, cj.x, s0.x);
        s0.y = fmaf(u.y, cj.y, s0.y);
        s0.z = fmaf(u.z, cj.z, s0.z);
        s0.w = fmaf(u.w, cj.w, s0.w);
        const int chunk = (cg >> 3) ^ ((row >> 1) & 3);
        unsigned* dst = U + row * ROWU32 + (chunk << 2) + ((cg & 4) >> 1);
        *(uint2*)dst = make_uint2(h2u(__floats2half2_rn(u.x, u.y)),
                                  h2u(__floats2half2_rn(u.z, u.w)));
    }
    // in-warp pass-0 reduce: lanes l, l+8, l+16, l+24 share channel group cg
    s0.x += __shfl_xor_sync(0xffffffffu, s0.x, 8);
    s0.y += __shfl_xor_sync(0xffffffffu, s0.y, 8);
    s0.z += __shfl_xor_sync(0xffffffffu, s0.z, 8);
    s0.w += __shfl_xor_sync(0xffffffffu, s0.w, 8);
    s0.x += __shfl_xor_sync(0xffffffffu, s0.x, 16);
    s0.y += __shfl_xor_sync(0xffffffffu, s0.y, 16);
    s0.z += __shfl_xor_sync(0xffffffffu, s0.z, 16);
    s0.w += __shfl_xor_sync(0xffffffffu, s0.w, 16);
    if (lane < 8)
        *(float4*)(RED + warp * OUT_CH + 4 * lane) = s0;

    // ---- 3 squash stages; stages 0,1 followed by an exp/softmax sweep ----
#pragma unroll 1
    for (int it = 0; it < 3; it++) {
        __syncthreads();                            // RED ready
        if (warp == 0) {
            float t = 0.f;
#pragma unroll
            for (int g = 0; g < NWARP; g++) t += RED[g * OUT_CH + lane];
            float n2 = warp_sum(t * t);
            float v = n2 * rcpa(1.f + n2) * rsqrtf(n2 + 1e-8f) * t;
            if (it == 2) {
                out[(size_t)blockIdx.x * OUT_CH + lane] = fmaf(0.5f, v, 0.5f);
            } else {
                float vl = v * LOG2E;
                float a = __shfl_sync(0xffffffffu, vl, (2 * lane) & 31);
                float b = __shfl_sync(0xffffffffu, vl, (2 * lane + 1) & 31);
                if (lane < 16) V2[lane] = h2u(__floats2half2_rn(a, b));
            }
        }
        if (it == 2) break;
        __syncthreads();                            // V2 ready, RED reads done

        // cache my 8 packed v-pairs in registers for the whole sweep
        unsigned v2loc[8];
#pragma unroll
        for (int p = 0; p < 8; p++) v2loc[p] = V2[8 * par + p];

        // hot sweep: each thread = 3 half-rows (16 channels), parity-fixed
        unsigned sp2[8];
#pragma unroll
        for (int p = 0; p < 8; p++) sp2[p] = 0u;

#pragma unroll
        for (int k = 0; k < HRPT; k++) {
            const int hh  = tid + THREADS * k;      // half-row index
            const int row = hh >> 1;                // hh&1 == par (768 even)
            const unsigned* rbase = U + row * ROWU32;
            const int sw = (row >> 1) & 3;
            const int h0 = 2 * par;                 // logical chunks h0, h0+1
            uint4 w0 = *(const uint4*)(rbase + (((h0)     ^ sw) << 2));
            uint4 w1 = *(const uint4*)(rbase + (((h0 + 1) ^ sw) << 2));
            unsigned up[8] = { w0.x, w0.y, w0.z, w0.w, w1.x, w1.y, w1.z, w1.w };

            __half2 da = __floats2half2_rn(0.f, 0.f);
            __half2 db = __floats2half2_rn(0.f, 0.f);
#pragma unroll
            for (int p = 0; p < 8; p++) {
                unsigned a  = h2u(__hmul2(u2h(up[p]), u2h(v2loc[p]))); // u*v*log2e
                unsigned e2 = ex2_h2(a);                               // exp x2
                if (p & 1) db = __hadd2(db, u2h(e2));
                else       da = __hadd2(da, u2h(e2));
                up[p] = h2u(__hmul2(u2h(up[p]), u2h(e2)));             // u*exp
            }
            float2 df = __half22float2(__hadd2(da, db));
            float dloc = df.x + df.y;                    // my 16 channels
            float drow = dloc + __shfl_xor_sync(0xffffffffu, dloc, 1); // +partner
            const __half2 r2 = __float2half2_rn(rcpa(drow));  // 1 rcp per half-row
#pragma unroll
            for (int p = 0; p < 8; p++)
                sp2[p] = h2u(__hfma2(u2h(up[p]), r2, u2h(sp2[p])));
        }

        // cross-lane reduce (same-parity lanes hold disjoint channel halves):
        // 1 packed fp16 level (xor16), then fp32 levels (xor8,4,2).
#pragma unroll
        for (int k2 = 0; k2 < 4; k2++) {            // xor16, packed
            unsigned send = (lane & 16) ? sp2[k2] : sp2[k2 + 4];
            unsigned recv = __shfl_xor_sync(0xffffffffu, send, 16);
            sp2[k2] = h2u(__hadd2(u2h((lane & 16) ? sp2[k2 + 4] : sp2[k2]),
                                  u2h(recv)));
        }
        float f[8];
#pragma unroll
        for (int k2 = 0; k2 < 4; k2++) {            // unpack to fp32
            float2 t2 = __half22float2(u2h(sp2[k2]));
            f[2 * k2] = t2.x; f[2 * k2 + 1] = t2.y;
        }
#pragma unroll
        for (int k2 = 0; k2 < 4; k2++) {            // xor8
            float send = (lane & 8) ? f[k2] : f[k2 + 4];
            float recv = __shfl_xor_sync(0xffffffffu, send, 8);
            f[k2] = ((lane & 8) ? f[k2 + 4] : f[k2]) + recv;
        }
#pragma unroll
        for (int k2 = 0; k2 < 2; k2++) {            // xor4
            float send = (lane & 4) ? f[k2] : f[k2 + 2];
            float recv = __shfl_xor_sync(0xffffffffu, send, 4);
            f[k2] = ((lane & 4) ? f[k2 + 2] : f[k2]) + recv;
        }
        {                                            // xor2
            float send = (lane & 2) ? f[0] : f[1];
            float recv = __shfl_xor_sync(0xffffffffu, send, 2);
            f[0] = ((lane & 2) ? f[1] : f[0]) + recv;
        }
        __syncthreads();                             // V2/RED readers done
        RED[warp * OUT_CH + 16 * (lane & 1) + ((lane >> 1) & 15)] = f[0];
    }
}

extern "C" void kernel_launch(void* const* d_in, const int* in_sizes, int n_in,
                              void* d_out, int out_size)
{
    const float* u_hat = (const float*)d_in[0];
    const float* c     = (const float*)d_in[1];
    const int n = in_sizes[0] / (NROWS * OUT_CH);      // 4096
    int sms = 148;
    cudaDeviceGetAttribute(&sms, cudaDevAttrMultiProcessorCount, 0);
    const int smem = (NROWS * ROWU32 + NWARP * OUT_CH + 16) * 4;  // ~76.9 KB
    cudaFuncSetAttribute(caps_kernel,
                         cudaFuncAttributeMaxDynamicSharedMemorySize, smem);
    caps_kernel<<<n, THREADS, smem>>>(u_hat, c, (float*)d_out, sms);
}

// round 16
// speedup vs baseline: 1.1490x; 1.1490x over previous
#include <cuda_runtime.h>
#include <cuda_fp16.h>
#include <cstdint>

#define NROWS   1152
#define OUT_CH  32
#define THREADS 768                // 24 warps; 2 CTAs/SM -> 48 warps
#define NWARP   24
#define HRPT    3                  // half-rows per thread (2304/768)
#define ROWU32  16                 // 64B/row, chunk-XOR swizzled
#define F4PT    12                 // float4 gmem loads per thread
#define LOG2E   1.4426950408889634f

__device__ __forceinline__ float rcpa(float x) {
    float y; asm("rcp.approx.f32 %0, %1;" : "=f"(y) : "f"(x)); return y;
}
__device__ __forceinline__ unsigned ex2_h2(unsigned a) {
    unsigned y; asm("ex2.approx.f16x2 %0, %1;" : "=r"(y) : "r"(a)); return y;
}
__device__ __forceinline__ float warp_sum(float v) {
    v += __shfl_xor_sync(0xffffffffu, v, 16);
    v += __shfl_xor_sync(0xffffffffu, v, 8);
    v += __shfl_xor_sync(0xffffffffu, v, 4);
    v += __shfl_xor_sync(0xffffffffu, v, 2);
    v += __shfl_xor_sync(0xffffffffu, v, 1);
    return v;
}
__device__ __forceinline__ unsigned h2u(__half2 h)  { return *(unsigned*)&h; }
__device__ __forceinline__ __half2  u2h(unsigned u) { return *(__half2*)&u; }

// One CTA per sample, 2 CTAs/SM (48 warps), half-row-per-thread sweeps.
// Change vs R12: the squash is computed REDUNDANTLY BY EVERY WARP (parallel,
// from RED via conflict-free LDS + lane shuffles) instead of by warp 0 alone
// with a smem broadcast — removes the per-stage single-warp serial section.
__global__ __launch_bounds__(THREADS, 2)
void caps_kernel(const float* __restrict__ u_hat,
                 const float* __restrict__ cprior,
                 float* __restrict__ out)
{
    extern __shared__ unsigned smu[];
    unsigned* U   = smu;                            // [1152][16] u32 (half2)
    float*    RED = (float*)(smu + NROWS * ROWU32); // [24][32] (pass-0 & sweeps)

    const int tid  = threadIdx.x;
    const int lane = tid & 31;
    const int warp = tid >> 5;
    const int par  = tid & 1;                       // half parity
    const size_t base = (size_t)blockIdx.x * (NROWS * OUT_CH);

    // ---- coalesced fp32 load, fused exact pass-0 dot, swizzled fp16 store ----
    const int cg = (4 * tid) & 31;
    const float4 cj = __ldg((const float4*)(cprior + cg));  // row-uniform prior
    float4 s0 = make_float4(0.f, 0.f, 0.f, 0.f);
#pragma unroll
    for (int k = 0; k < F4PT; k++) {
        const int e   = (tid + THREADS * k) << 2;
        const int row = e >> 5;
        const float4 u = __ldg((const float4*)(u_hat + base + e));
        s0.x = fmaf(u.x, cj.x, s0.x);
        s0.y = fmaf(u.y, cj.y, s0.y);
        s0.z = fmaf(u.z, cj.z, s0.z);
        s0.w = fmaf(u.w, cj.w, s0.w);
        const int chunk = (cg >> 3) ^ ((row >> 1) & 3);
        unsigned* dst = U + row * ROWU32 + (chunk << 2) + ((cg & 4) >> 1);
        *(uint2*)dst = make_uint2(h2u(__floats2half2_rn(u.x, u.y)),
                                  h2u(__floats2half2_rn(u.z, u.w)));
    }
    // in-warp pass-0 reduce: lanes l, l+8, l+16, l+24 share channel group cg
    s0.x += __shfl_xor_sync(0xffffffffu, s0.x, 8);
    s0.y += __shfl_xor_sync(0xffffffffu, s0.y, 8);
    s0.z += __shfl_xor_sync(0xffffffffu, s0.z, 8);
    s0.w += __shfl_xor_sync(0xffffffffu, s0.w, 8);
    s0.x += __shfl_xor_sync(0xffffffffu, s0.x, 16);
    s0.y += __shfl_xor_sync(0xffffffffu, s0.y, 16);
    s0.z += __shfl_xor_sync(0xffffffffu, s0.z, 16);
    s0.w += __shfl_xor_sync(0xffffffffu, s0.w, 16);
    if (lane < 8)
        *(float4*)(RED + warp * OUT_CH + 4 * lane) = s0;

    // ---- 3 squash stages; stages 0,1 followed by an exp/softmax sweep ----
#pragma unroll 1
    for (int it = 0; it < 3; it++) {
        __syncthreads();                            // RED writes visible

        // every warp computes the squash (parallel, redundant; lane = channel)
        float t = 0.f;
#pragma unroll
        for (int g = 0; g < NWARP; g++) t += RED[g * OUT_CH + lane];
        float n2 = warp_sum(t * t);
        float v = n2 * rcpa(1.f + n2) * rsqrtf(n2 + 1e-8f) * t;

        if (it == 2) {
            if (warp == 0)
                out[(size_t)blockIdx.x * OUT_CH + lane] = fmaf(0.5f, v, 0.5f);
            break;
        }

        // build my packed v*log2e pairs for channels 16*par .. 16*par+15
        const float vl = v * LOG2E;
        unsigned v2loc[8];
#pragma unroll
        for (int p = 0; p < 8; p++) {
            float a = __shfl_sync(0xffffffffu, vl, 16 * par + 2 * p);
            float b = __shfl_sync(0xffffffffu, vl, 16 * par + 2 * p + 1);
            v2loc[p] = h2u(__floats2half2_rn(a, b));
        }

        // hot sweep: each thread = 3 half-rows (16 channels), parity-fixed
        unsigned sp2[8];
#pragma unroll
        for (int p = 0; p < 8; p++) sp2[p] = 0u;

#pragma unroll
        for (int k = 0; k < HRPT; k++) {
            const int hh  = tid + THREADS * k;      // half-row index
            const int row = hh >> 1;                // hh&1 == par (768 even)
            const unsigned* rbase = U + row * ROWU32;
            const int sw = (row >> 1) & 3;
            const int h0 = 2 * par;                 // logical chunks h0, h0+1
            uint4 w0 = *(const uint4*)(rbase + (((h0)     ^ sw) << 2));
            uint4 w1 = *(const uint4*)(rbase + (((h0 + 1) ^ sw) << 2));
            unsigned up[8] = { w0.x, w0.y, w0.z, w0.w, w1.x, w1.y, w1.z, w1.w };

            __half2 da = __floats2half2_rn(0.f, 0.f);
            __half2 db = __floats2half2_rn(0.f, 0.f);
#pragma unroll
            for (int p = 0; p < 8; p++) {
                unsigned a  = h2u(__hmul2(u2h(up[p]), u2h(v2loc[p]))); // u*v*log2e
                unsigned e2 = ex2_h2(a);                               // exp x2
                if (p & 1) db = __hadd2(db, u2h(e2));
                else       da = __hadd2(da, u2h(e2));
                up[p] = h2u(__hmul2(u2h(up[p]), u2h(e2)));             // u*exp
            }
            float2 df = __half22float2(__hadd2(da, db));
            float dloc = df.x + df.y;                    // my 16 channels
            float drow = dloc + __shfl_xor_sync(0xffffffffu, dloc, 1); // +partner
            const __half2 r2 = __float2half2_rn(rcpa(drow));  // 1 rcp per half-row
#pragma unroll
            for (int p = 0; p < 8; p++)
                sp2[p] = h2u(__hfma2(u2h(up[p]), r2, u2h(sp2[p])));
        }

        // cross-lane reduce (same-parity lanes hold disjoint channel halves):
        // 1 packed fp16 level (xor16), then fp32 levels (xor8,4,2).
#pragma unroll
        for (int k2 = 0; k2 < 4; k2++) {            // xor16, packed
            unsigned send = (lane & 16) ? sp2[k2] : sp2[k2 + 4];
            unsigned recv = __shfl_xor_sync(0xffffffffu, send, 16);
            sp2[k2] = h2u(__hadd2(u2h((lane & 16) ? sp2[k2 + 4] : sp2[k2]),
                                  u2h(recv)));
        }
        float f[8];
#pragma unroll
        for (int k2 = 0; k2 < 4; k2++) {            // unpack to fp32
            float2 t2 = __half22float2(u2h(sp2[k2]));
            f[2 * k2] = t2.x; f[2 * k2 + 1] = t2.y;
        }
#pragma unroll
        for (int k2 = 0; k2 < 4; k2++) {            // xor8
            float send = (lane & 8) ? f[k2] : f[k2 + 4];
            float recv = __shfl_xor_sync(0xffffffffu, send, 8);
            f[k2] = ((lane & 8) ? f[k2 + 4] : f[k2]) + recv;
        }
#pragma unroll
        for (int k2 = 0; k2 < 2; k2++) {            // xor4
            float send = (lane & 4) ? f[k2] : f[k2 + 2];
            float recv = __shfl_xor_sync(0xffffffffu, send, 4);
            f[k2] = ((lane & 4) ? f[k2 + 2] : f[k2]) + recv;
        }
        {                                            // xor2
            float send = (lane & 2) ? f[0] : f[1];
            float recv = __shfl_xor_sync(0xffffffffu, send, 2);
            f[0] = ((lane & 2) ? f[1] : f[0]) + recv;
        }
        // all RED reads happened at stage start (before the sweep); this
        // barrier orders them before the overwrite below.
        __syncthreads();
        RED[warp * OUT_CH + 16 * (lane & 1) + ((lane >> 1) & 15)] = f[0];
    }
}

extern "C" void kernel_launch(void* const* d_in, const int* in_sizes, int n_in,
                              void* d_out, int out_size)
{
    const float* u_hat = (const float*)d_in[0];
    const float* c     = (const float*)d_in[1];
    const int n = in_sizes[0] / (NROWS * OUT_CH);      // 4096
    const int smem = (NROWS * ROWU32 + NWARP * OUT_CH) * 4;   // ~76.8 KB
    cudaFuncSetAttribute(caps_kernel,
                         cudaFuncAttributeMaxDynamicSharedMemorySize, smem);
    caps_kernel<<<n, THREADS, smem>>>(u_hat, c, (float*)d_out);
}

// round 17
// speedup vs baseline: 1.3423x; 1.1683x over previous
#include <cuda_runtime.h>
#include <cuda_fp16.h>
#include <cstdint>

#define NROWS   1152
#define OUT_CH  32
#define THREADS 768                // 24 warps; 2 CTAs/SM -> 48 warps
#define NWARP   24
#define HRPT    3                  // half-rows per thread (2304/768)
#define ROWU32  16                 // 64B/row, chunk-XOR swizzled
#define F4PT    12                 // float4 gmem loads per thread
#define REDP    28                 // RED row pad (floats): conflict-free LDS.128
#define LOG2E   1.4426950408889634f

__device__ __forceinline__ float rcpa(float x) {
    float y; asm("rcp.approx.f32 %0, %1;" : "=f"(y) : "f"(x)); return y;
}
__device__ __forceinline__ unsigned ex2_h2(unsigned a) {
    unsigned y; asm("ex2.approx.f16x2 %0, %1;" : "=r"(y) : "r"(a)); return y;
}
__device__ __forceinline__ float warp_sum(float v) {
    v += __shfl_xor_sync(0xffffffffu, v, 16);
    v += __shfl_xor_sync(0xffffffffu, v, 8);
    v += __shfl_xor_sync(0xffffffffu, v, 4);
    v += __shfl_xor_sync(0xffffffffu, v, 2);
    v += __shfl_xor_sync(0xffffffffu, v, 1);
    return v;
}
__device__ __forceinline__ unsigned h2u(__half2 h)  { return *(unsigned*)&h; }
__device__ __forceinline__ __half2  u2h(unsigned u) { return *(__half2*)&u; }

// One CTA per sample, 2 CTAs/SM (48 warps), half-row-per-thread sweeps (R12).
// Delta vs R12: RED is transposed to [32 ch][28] so warp0's squash gather is
// 6 conflict-free LDS.128 per lane instead of 24 strided LDS.32 — shrinks the
// per-stage single-warp serial section without adding work to other warps.
__global__ __launch_bounds__(THREADS, 2)
void caps_kernel(const float* __restrict__ u_hat,
                 const float* __restrict__ cprior,
                 float* __restrict__ out)
{
    extern __shared__ unsigned smu[];
    unsigned* U   = smu;                            // [1152][16] u32 (half2)
    float*    RED = (float*)(smu + NROWS * ROWU32); // [32][28] ch-major partials
    unsigned* V2  = (unsigned*)(RED + OUT_CH * REDP); // [16] packed v*log2e

    const int tid  = threadIdx.x;
    const int lane = tid & 31;
    const int warp = tid >> 5;
    const int par  = tid & 1;                       // half parity
    const size_t base = (size_t)blockIdx.x * (NROWS * OUT_CH);

    // ---- coalesced fp32 load, fused exact pass-0 dot, swizzled fp16 store ----
    const int cg = (4 * tid) & 31;
    const float4 cj = __ldg((const float4*)(cprior + cg));  // row-uniform prior
    float4 s0 = make_float4(0.f, 0.f, 0.f, 0.f);
#pragma unroll
    for (int k = 0; k < F4PT; k++) {
        const int e   = (tid + THREADS * k) << 2;
        const int row = e >> 5;
        const float4 u = __ldg((const float4*)(u_hat + base + e));
        s0.x = fmaf(u.x, cj.x, s0.x);
        s0.y = fmaf(u.y, cj.y, s0.y);
        s0.z = fmaf(u.z, cj.z, s0.z);
        s0.w = fmaf(u.w, cj.w, s0.w);
        const int chunk = (cg >> 3) ^ ((row >> 1) & 3);
        unsigned* dst = U + row * ROWU32 + (chunk << 2) + ((cg & 4) >> 1);
        *(uint2*)dst = make_uint2(h2u(__floats2half2_rn(u.x, u.y)),
                                  h2u(__floats2half2_rn(u.z, u.w)));
    }
    // in-warp pass-0 reduce: lanes l, l+8, l+16, l+24 share channel group cg
    s0.x += __shfl_xor_sync(0xffffffffu, s0.x, 8);
    s0.y += __shfl_xor_sync(0xffffffffu, s0.y, 8);
    s0.z += __shfl_xor_sync(0xffffffffu, s0.z, 8);
    s0.w += __shfl_xor_sync(0xffffffffu, s0.w, 8);
    s0.x += __shfl_xor_sync(0xffffffffu, s0.x, 16);
    s0.y += __shfl_xor_sync(0xffffffffu, s0.y, 16);
    s0.z += __shfl_xor_sync(0xffffffffu, s0.z, 16);
    s0.w += __shfl_xor_sync(0xffffffffu, s0.w, 16);
    if (lane < 8) {                  // lane l holds channels 4l..4l+3
        float* rp = RED + (4 * lane) * REDP + warp;
        rp[0]        = s0.x;
        rp[REDP]     = s0.y;
        rp[2 * REDP] = s0.z;
        rp[3 * REDP] = s0.w;
    }

    // ---- 3 squash stages; stages 0,1 followed by an exp/softmax sweep ----
#pragma unroll 1
    for (int it = 0; it < 3; it++) {
        __syncthreads();                            // RED ready
        if (warp == 0) {
            // lane = channel: 6 conflict-free LDS.128 gather the 24 partials
            const float4* rrow = (const float4*)(RED + lane * REDP);
            float t = 0.f;
#pragma unroll
            for (int q = 0; q < 6; q++) {
                float4 a = rrow[q];
                t += (a.x + a.y) + (a.z + a.w);
            }
            float n2 = warp_sum(t * t);
            float v = n2 * rcpa(1.f + n2) * rsqrtf(n2 + 1e-8f) * t;
            if (it == 2) {
                out[(size_t)blockIdx.x * OUT_CH + lane] = fmaf(0.5f, v, 0.5f);
            } else {
                float vl = v * LOG2E;
                float a = __shfl_sync(0xffffffffu, vl, (2 * lane) & 31);
                float b = __shfl_sync(0xffffffffu, vl, (2 * lane + 1) & 31);
                if (lane < 16) V2[lane] = h2u(__floats2half2_rn(a, b));
            }
        }
        if (it == 2) break;
        __syncthreads();                            // V2 ready, RED reads done

        // cache my 8 packed v-pairs in registers for the whole sweep
        unsigned v2loc[8];
#pragma unroll
        for (int p = 0; p < 8; p++) v2loc[p] = V2[8 * par + p];

        // hot sweep: each thread = 3 half-rows (16 channels), parity-fixed
        unsigned sp2[8];
#pragma unroll
        for (int p = 0; p < 8; p++) sp2[p] = 0u;

#pragma unroll
        for (int k = 0; k < HRPT; k++) {
            const int hh  = tid + THREADS * k;      // half-row index
            const int row = hh >> 1;                // hh&1 == par (768 even)
            const unsigned* rbase = U + row * ROWU32;
            const int sw = (row >> 1) & 3;
            const int h0 = 2 * par;                 // logical chunks h0, h0+1
            uint4 w0 = *(const uint4*)(rbase + (((h0)     ^ sw) << 2));
            uint4 w1 = *(const uint4*)(rbase + (((h0 + 1) ^ sw) << 2));
            unsigned up[8] = { w0.x, w0.y, w0.z, w0.w, w1.x, w1.y, w1.z, w1.w };

            __half2 da = __floats2half2_rn(0.f, 0.f);
            __half2 db = __floats2half2_rn(0.f, 0.f);
#pragma unroll
            for (int p = 0; p < 8; p++) {
                unsigned a  = h2u(__hmul2(u2h(up[p]), u2h(v2loc[p]))); // u*v*log2e
                unsigned e2 = ex2_h2(a);                               // exp x2
                if (p & 1) db = __hadd2(db, u2h(e2));
                else       da = __hadd2(da, u2h(e2));
                up[p] = h2u(__hmul2(u2h(up[p]), u2h(e2)));             // u*exp
            }
            float2 df = __half22float2(__hadd2(da, db));
            float dloc = df.x + df.y;                    // my 16 channels
            float drow = dloc + __shfl_xor_sync(0xffffffffu, dloc, 1); // +partner
            const __half2 r2 = __float2half2_rn(rcpa(drow));  // 1 rcp per half-row
#pragma unroll
            for (int p = 0; p < 8; p++)
                sp2[p] = h2u(__hfma2(u2h(up[p]), r2, u2h(sp2[p])));
        }

        // cross-lane reduce (same-parity lanes hold disjoint channel halves):
        // 1 packed fp16 level (xor16), then fp32 levels (xor8,4,2).
#pragma unroll
        for (int k2 = 0; k2 < 4; k2++) {            // xor16, packed
            unsigned send = (lane & 16) ? sp2[k2] : sp2[k2 + 4];
            unsigned recv = __shfl_xor_sync(0xffffffffu, send, 16);
            sp2[k2] = h2u(__hadd2(u2h((lane & 16) ? sp2[k2 + 4] : sp2[k2]),
                                  u2h(recv)));
        }
        float f[8];
#pragma unroll
        for (int k2 = 0; k2 < 4; k2++) {            // unpack to fp32
            float2 t2 = __half22float2(u2h(sp2[k2]));
            f[2 * k2] = t2.x; f[2 * k2 + 1] = t2.y;
        }
#pragma unroll
        for (int k2 = 0; k2 < 4; k2++) {            // xor8
            float send = (lane & 8) ? f[k2] : f[k2 + 4];
            float recv = __shfl_xor_sync(0xffffffffu, send, 8);
            f[k2] = ((lane & 8) ? f[k2 + 4] : f[k2]) + recv;
        }
#pragma unroll
        for (int k2 = 0; k2 < 2; k2++) {            // xor4
            float send = (lane & 4) ? f[k2] : f[k2 + 2];
            float recv = __shfl_xor_sync(0xffffffffu, send, 4);
            f[k2] = ((lane & 4) ? f[k2 + 2] : f[k2]) + recv;
        }
        {                                            // xor2
            float send = (lane & 2) ? f[0] : f[1];
            float recv = __shfl_xor_sync(0xffffffffu, send, 2);
            f[0] = ((lane & 2) ? f[1] : f[0]) + recv;
        }
        __syncthreads();                             // V2/RED readers done
        // lane's channel: 16*(lane&1) + (lane>>1); write RED[ch][warp]
        RED[(16 * (lane & 1) + ((lane >> 1) & 15)) * REDP + warp] = f[0];
    }
}

extern "C" void kernel_launch(void* const* d_in, const int* in_sizes, int n_in,
                              void* d_out, int out_size)
{
    const float* u_hat = (const float*)d_in[0];
    const float* c     = (const float*)d_in[1];
    const int n = in_sizes[0] / (NROWS * OUT_CH);      // 4096
    const int smem = (NROWS * ROWU32 + OUT_CH * REDP + 16) * 4;  // ~77.4 KB
    cudaFuncSetAttribute(caps_kernel,
                         cudaFuncAttributeMaxDynamicSharedMemorySize, smem);
    caps_kernel<<<n, THREADS, smem>>>(u_hat, c, (float*)d_out);
}